// round 7
// baseline (speedup 1.0000x reference)
#include <cuda_runtime.h>

#define MAXQ   4096
#define MAXM   100000
#define TILE   512
#define MARGIN 0.0625f

// Scratch (static __device__ — no runtime allocation)
__device__ float4      g_q[MAXQ];            // x, y, z, |q|^2
__device__ unsigned    g_dmin[MAXQ];         // monotonic-mapped min of (|m|^2 - 2 q.m)
__device__ ulonglong2  g_means2[2 * MAXM];   // per mean: {(-2x,-2x),(-2y,-2y)} , {(-2z,-2z),(m2,m2)}

__device__ __forceinline__ unsigned long long pk(float lo, float hi) {
    return (unsigned long long)__float_as_uint(lo) |
           ((unsigned long long)__float_as_uint(hi) << 32);
}

// Packed fp32x2 FMA (Blackwell): d = a*b + c per 32-bit lane
__device__ __forceinline__ unsigned long long fma2(unsigned long long a,
                                                   unsigned long long b,
                                                   unsigned long long c) {
    unsigned long long d;
    asm("fma.rn.f32x2 %0, %1, %2, %3;" : "=l"(d) : "l"(a), "l"(b), "l"(c));
    return d;
}

// Sign-aware monotonic float<->uint mapping (so atomicMin on uint == min on float,
// including negative values from catastrophic cancellation)
__device__ __forceinline__ unsigned fmap(float f) {
    unsigned u = __float_as_uint(f);
    return (u & 0x80000000u) ? ~u : (u ^ 0x80000000u);
}
__device__ __forceinline__ float finv(unsigned k) {
    unsigned u = (k & 0x80000000u) ? (k ^ 0x80000000u) : ~k;
    return __uint_as_float(u);
}

// ---------------------------------------------------------------------------
// Kernel 1: transform outputs -> query points q (and |q|^2), init min slots
// retrajs[b,n,i] = s_b * sum_j outputs[b,n,j] * c2w[b,i,j]  +  c2w[b,i,3]
// ---------------------------------------------------------------------------
__global__ void qprep_kernel(const float* __restrict__ outputs,
                             const float* __restrict__ c2ws,
                             const float* __restrict__ scales,
                             int N, int Qtot) {
    int idx = blockIdx.x * blockDim.x + threadIdx.x;
    if (idx >= MAXQ) return;
    if (idx < Qtot) {
        int b = idx / N, n = idx % N;
        float s = scales[b];
        const float* o = outputs + ((size_t)b * N + n) * 3;
        const float* c = c2ws + (size_t)b * 16;
        float ox = o[0], oy = o[1], oz = o[2];
        float qx = fmaf(s, fmaf(ox, c[0], fmaf(oy, c[1], oz * c[2])),  c[3]);
        float qy = fmaf(s, fmaf(ox, c[4], fmaf(oy, c[5], oz * c[6])),  c[7]);
        float qz = fmaf(s, fmaf(ox, c[8], fmaf(oy, c[9], oz * c[10])), c[11]);
        g_q[idx] = make_float4(qx, qy, qz, qx * qx + qy * qy + qz * qz);
    } else {
        g_q[idx] = make_float4(0.f, 0.f, 0.f, 0.f);
    }
    g_dmin[idx] = 0xFFFFFFFFu;
}

// ---------------------------------------------------------------------------
// Kernel 2: pack means into duplicated f32x2 lanes: (-2x,-2x,-2y,-2y),(-2z,-2z,m2,m2)
// ---------------------------------------------------------------------------
__global__ void mprep_kernel(const float* __restrict__ means, int M) {
    int m = blockIdx.x * blockDim.x + threadIdx.x;
    if (m >= M) return;
    float x = means[3 * m + 0];
    float y = means[3 * m + 1];
    float z = means[3 * m + 2];
    float w = fmaf(x, x, fmaf(y, y, z * z));
    g_means2[2 * m + 0] = make_ulonglong2(pk(-2.f * x, -2.f * x), pk(-2.f * y, -2.f * y));
    g_means2[2 * m + 1] = make_ulonglong2(pk(-2.f * z, -2.f * z), pk(w, w));
}

// ---------------------------------------------------------------------------
// Kernel 3 (hot): per-q min over this block's chunk of means.
// Each thread owns 16 consecutive q's as 8 f32x2 triples. For each mean:
//   t = m2 - 2 q.m  (3 packed FMAs, shared packed mean operands from smem)
// ---------------------------------------------------------------------------
__global__ void __launch_bounds__(256, 2) nn_min_kernel(int M) {
    __shared__ ulonglong2 sm[2 * TILE];   // 16 KB

    const int tid  = threadIdx.x;
    const int base = tid * 16;

    unsigned long long QX[8], QY[8], QZ[8];
#pragma unroll
    for (int p = 0; p < 8; ++p) {
        float4 a = g_q[base + 2 * p];
        float4 b = g_q[base + 2 * p + 1];
        QX[p] = pk(a.x, b.x);
        QY[p] = pk(a.y, b.y);
        QZ[p] = pk(a.z, b.z);
    }

    float best[16];
#pragma unroll
    for (int k = 0; k < 16; ++k) best[k] = __int_as_float(0x7f800000);  // +inf

    const int chunk = (M + gridDim.x - 1) / gridDim.x;
    const int start = blockIdx.x * chunk;
    const int end   = min(start + chunk, M);

    for (int t0 = start; t0 < end; t0 += TILE) {
        const int cnt = min(TILE, end - t0);
        __syncthreads();
        for (int i = tid; i < cnt * 2; i += 256)
            sm[i] = g_means2[(size_t)t0 * 2 + i];
        __syncthreads();

        for (int j = 0; j < cnt; ++j) {
            const ulonglong2 e0 = sm[2 * j];       // (A=-2x dup, B=-2y dup)
            const ulonglong2 e1 = sm[2 * j + 1];   // (C=-2z dup, W=m2  dup)
#pragma unroll
            for (int p = 0; p < 8; ++p) {
                unsigned long long acc = fma2(QZ[p], e1.x, e1.y);
                acc = fma2(QY[p], e0.y, acc);
                acc = fma2(QX[p], e0.x, acc);
                float lo = __uint_as_float((unsigned)acc);
                float hi = __uint_as_float((unsigned)(acc >> 32));
                best[2 * p]     = fminf(best[2 * p],     lo);
                best[2 * p + 1] = fminf(best[2 * p + 1], hi);
            }
        }
    }

#pragma unroll
    for (int k = 0; k < 16; ++k)
        atomicMin(&g_dmin[base + k], fmap(best[k]));
}

// ---------------------------------------------------------------------------
// Kernel 4: unmap, add |q|^2, clamp, hinge, mean -> out[0]
// ---------------------------------------------------------------------------
__global__ void reduce_kernel(float* __restrict__ out, int Qtot) {
    __shared__ float wsum[32];
    const int tid = threadIdx.x;

    float s = 0.f;
    for (int idx = tid; idx < Qtot; idx += blockDim.x) {
        float t  = finv(g_dmin[idx]);
        float d2 = t + g_q[idx].w;
        float d  = fmaxf(d2, 0.f);
        s += fmaxf(MARGIN - d, 0.f);
    }
#pragma unroll
    for (int o = 16; o; o >>= 1) s += __shfl_down_sync(0xFFFFFFFFu, s, o);
    if ((tid & 31) == 0) wsum[tid >> 5] = s;
    __syncthreads();
    if (tid < 32) {
        float v = (tid < (int)(blockDim.x >> 5)) ? wsum[tid] : 0.f;
#pragma unroll
        for (int o = 16; o; o >>= 1) v += __shfl_down_sync(0xFFFFFFFFu, v, o);
        if (tid == 0) out[0] = v / (float)Qtot;
    }
}

extern "C" void kernel_launch(void* const* d_in, const int* in_sizes, int n_in,
                              void* d_out, int out_size) {
    const float* outputs = (const float*)d_in[0];  // (B, N, 3)
    const float* c2ws    = (const float*)d_in[1];  // (B, 4, 4)
    const float* scales  = (const float*)d_in[2];  // (B,)
    const float* means   = (const float*)d_in[3];  // (M, 3)

    int B = in_sizes[2];
    int Q = in_sizes[0] / 3;         // B*N
    int N = (B > 0) ? (Q / B) : 0;
    int M = in_sizes[3] / 3;
    if (Q > MAXQ) Q = MAXQ;
    if (M > MAXM) M = MAXM;

    qprep_kernel<<<(MAXQ + 255) / 256, 256>>>(outputs, c2ws, scales, N, Q);
    mprep_kernel<<<(M + 255) / 256, 256>>>(means, M);
    nn_min_kernel<<<304, 256>>>(M);
    reduce_kernel<<<1, 512>>>((float*)d_out, Q);
}